// round 5
// baseline (speedup 1.0000x reference)
#include <cuda_runtime.h>

// Sinkhorn OT loss on 64x64 pooled grids, 2-CTA cluster per batch.
// K = exp(-C/0.1): exact (to fp32) as two 3-tap separable passes, W1=exp(-10).
// (Dropping the W1^2 cross term was measured to amplify ~4e5x through the
// iteration -> rel_err 9e-4; the two-phase form keeps it at ~1e-6.)
// Each CTA owns 32 rows; the one cross-CTA halo row per halfstep travels via
// st.shared::cluster + remote mbarrier arrive (release.cluster), consumed next
// halfstep with try_wait.parity.acquire.cluster. Producer sends out-rows, the
// consumer recomputes H of the halo row locally -> 1 halfstep of latency slack.

#define NBATCH 16
#define ITERS  50
#define EPS    1e-8f
#define W1     4.5399929762484854e-05f   // exp(-10)

__device__ float g_pooled[2][NBATCH][4096];
__device__ float g_costs[NBATCH * 2];
__device__ int   g_done;

// ---------------------------------------------------------------- pooling
__global__ __launch_bounds__(256) void pool_kernel(const float* __restrict__ pred,
                                                   const float* __restrict__ gt) {
    const int bid    = blockIdx.x;          // 0..511
    const int tensor = bid >> 8;
    const int batch  = (bid >> 4) & 15;
    const int rb     = bid & 15;
    const float* src = (tensor ? gt : pred) + (size_t)batch * 262144;

    const int pr = rb * 4 + (threadIdx.x >> 6);
    const int pc = threadIdx.x & 63;
    const float4* p = (const float4*)(src + (size_t)pr * 4096 + pc * 8);

    float s = 0.f;
#pragma unroll
    for (int y = 0; y < 8; ++y) {
        float4 v0 = p[y * 128];
        float4 v1 = p[y * 128 + 1];
        s += (v0.x + v0.y) + (v0.z + v0.w) + (v1.x + v1.y) + (v1.z + v1.w);
    }
    g_pooled[tensor][batch][pr * 64 + pc] = s;
}

// ---------------------------------------------------------------- helpers
__device__ __forceinline__ unsigned smem_u32(const void* p) {
    unsigned a;
    asm("{ .reg .u64 t; cvta.to.shared.u64 t, %1; cvt.u32.u64 %0, t; }"
        : "=r"(a) : "l"(p));
    return a;
}
__device__ __forceinline__ unsigned mapa_u32(unsigned addr, unsigned rank) {
    unsigned r;
    asm("mapa.shared::cluster.u32 %0, %1, %2;" : "=r"(r) : "r"(addr), "r"(rank));
    return r;
}
__device__ __forceinline__ void mbar_wait_acq_cluster(unsigned mb, unsigned parity) {
    asm volatile(
        "{\n\t"
        ".reg .pred P;\n"
        "W_%=:\n\t"
        "mbarrier.try_wait.parity.acquire.cluster.shared::cta.b64 P, [%0], %1;\n\t"
        "@!P bra W_%=;\n\t"
        "}" :: "r"(mb), "r"(parity) : "memory");
}

__device__ __forceinline__ float blockReduceSum256(float val, float* red) {
#pragma unroll
    for (int o = 16; o; o >>= 1) val += __shfl_xor_sync(0xffffffffu, val, o);
    const int w = threadIdx.x >> 5, l = threadIdx.x & 31;
    __syncthreads();
    if (l == 0) red[w] = val;
    __syncthreads();
    float s = ((red[0] + red[1]) + (red[2] + red[3]))
            + ((red[4] + red[5]) + (red[6] + red[7]));
    __syncthreads();
    return s;
}

// ---------------------------------------------------------------- sinkhorn
__global__ __launch_bounds__(256, 1) __cluster_dims__(2, 1, 1)
void sinkhorn_kernel(float* __restrict__ out) {
    __shared__ __align__(16) float HS[2][34][64];   // H field, double-buffered; rows 0,33 = 0 pads
    __shared__ __align__(16) float halo[2][64];     // peer-written input-halo rows, per-slot
    __shared__ float red[8];
    __shared__ float xpart[2];
    __shared__ unsigned long long mbar[2];

    const int t     = threadIdx.x;
    const int wid   = t >> 5, l = t & 31;
    const int seg   = l & 15;
    const int band  = 2 * wid + (l >> 4);   // 0..15, 2 local rows each
    const int c0    = seg * 4;
    const int rank  = blockIdx.x & 1;       // == cluster_ctarank for 1-D cluster
    const int batch = blockIdx.x >> 1;
    const int bband = rank ? 0 : 15;        // band adjacent to the other CTA
    const int bwarp = rank ? 0 : 7;
    const unsigned peer = rank ^ 1;

    if (t == 0) {
        asm volatile("mbarrier.init.shared.b64 [%0], %1;"
                     :: "r"(smem_u32(&mbar[0])), "r"(16) : "memory");
        asm volatile("mbarrier.init.shared.b64 [%0], %1;"
                     :: "r"(smem_u32(&mbar[1])), "r"(16) : "memory");
    }
    for (int i = t; i < 2 * 34 * 64; i += 256) ((float*)HS)[i] = 0.f;  // zero pads
    if (t < 64) halo[0][t] = 1.f;   // initial u == 1 on the remote halo row

    const unsigned mb0 = smem_u32(&mbar[0]);
    const unsigned mb1 = smem_u32(&mbar[1]);
    const unsigned rmb[2]   = { mapa_u32(mb0, peer), mapa_u32(mb1, peer) };
    const unsigned rhalo[2] = { mapa_u32(smem_u32(&halo[0][0]), peer) + (unsigned)c0 * 4u,
                                mapa_u32(smem_u32(&halo[1][0]), peer) + (unsigned)c0 * 4u };

    // ---- load my half of the pooled grids (global rows rank*32 .. +31) ----
    float a[2][4], b[2][4], u[2][4], v[2][4];
    float asum = 0.f, bsum = 0.f;
    {
        const float* pa = &g_pooled[0][batch][(rank * 32 + band * 2) * 64 + c0];
        const float* pb = &g_pooled[1][batch][(rank * 32 + band * 2) * 64 + c0];
#pragma unroll
        for (int i = 0; i < 2; ++i) {
            const float4 x = *(const float4*)(pa + i * 64);
            const float4 y = *(const float4*)(pb + i * 64);
            a[i][0] = x.x; a[i][1] = x.y; a[i][2] = x.z; a[i][3] = x.w;
            b[i][0] = y.x; b[i][1] = y.y; b[i][2] = y.z; b[i][3] = y.w;
            asum += (x.x + x.y) + (x.z + x.w);
            bsum += (y.x + y.y) + (y.z + y.w);
        }
    }
    asum = blockReduceSum256(asum, red);
    bsum = blockReduceSum256(bsum, red);

    // cross-CTA partial-sum exchange (one-time)
    if (t == 0) {
        const unsigned rxp = mapa_u32(smem_u32(&xpart[0]), peer);
        asm volatile("st.shared::cluster.f32 [%0], %1;" :: "r"(rxp),      "f"(asum) : "memory");
        asm volatile("st.shared::cluster.f32 [%0], %1;" :: "r"(rxp + 4u), "f"(bsum) : "memory");
    }
    asm volatile("barrier.cluster.arrive.aligned;" ::: "memory");
    asm volatile("barrier.cluster.wait.aligned;"   ::: "memory");

    // canonical rank0+rank1 order -> both CTAs get bitwise-identical totals
    const float at0 = rank ? xpart[0] : asum;
    const float at1 = rank ? asum     : xpart[0];
    const float bt0 = rank ? xpart[1] : bsum;
    const float bt1 = rank ? bsum     : xpart[1];
    const float asumT = at0 + at1;
    const float bsumT = bt0 + bt1;
    const float ra  = 1.f / fmaxf(asumT, 1e-8f);
    const float rbv = 1.f / fmaxf(bsumT, 1e-8f);
#pragma unroll
    for (int i = 0; i < 2; ++i)
#pragma unroll
        for (int j = 0; j < 4; ++j) {
            a[i][j] *= ra; b[i][j] *= rbv; u[i][j] = 1.f;
        }

    int pha[2] = {0, 0};

    // out = tgt / (Ve(He(in)) + eps); slot s doubles as HS buffer index.
    auto halfstep = [&](float (&o)[2][4], const float (&tg)[2][4],
                        const float (&in)[2][4], const int s, const bool do_wait) {
        float H0[4], H1[4];
        {
            float lf0 = __shfl_up_sync(0xffffffffu, in[0][3], 1, 16);
            float rt0 = __shfl_down_sync(0xffffffffu, in[0][0], 1, 16);
            float lf1 = __shfl_up_sync(0xffffffffu, in[1][3], 1, 16);
            float rt1 = __shfl_down_sync(0xffffffffu, in[1][0], 1, 16);
            if (seg == 0)  { lf0 = 0.f; lf1 = 0.f; }
            if (seg == 15) { rt0 = 0.f; rt1 = 0.f; }
            H0[0] = fmaf(W1, lf0,      fmaf(W1, in[0][1], in[0][0]));
            H0[1] = fmaf(W1, in[0][0], fmaf(W1, in[0][2], in[0][1]));
            H0[2] = fmaf(W1, in[0][1], fmaf(W1, in[0][3], in[0][2]));
            H0[3] = fmaf(W1, in[0][2], fmaf(W1, rt0,      in[0][3]));
            H1[0] = fmaf(W1, lf1,      fmaf(W1, in[1][1], in[1][0]));
            H1[1] = fmaf(W1, in[1][0], fmaf(W1, in[1][2], in[1][1]));
            H1[2] = fmaf(W1, in[1][1], fmaf(W1, in[1][3], in[1][2]));
            H1[3] = fmaf(W1, in[1][2], fmaf(W1, rt1,      in[1][3]));
        }
        *(float4*)&HS[s][2 * band + 1][c0] = make_float4(H0[0], H0[1], H0[2], H0[3]);
        *(float4*)&HS[s][2 * band + 2][c0] = make_float4(H1[0], H1[1], H1[2], H1[3]);

        // boundary warp: wait for peer's input-halo row, build its H locally
        float Hh[4] = {0.f, 0.f, 0.f, 0.f};
        if (wid == bwarp) {
            if (do_wait) mbar_wait_acq_cluster(s ? mb1 : mb0, (unsigned)pha[s]);
            const float4 hv = *(const float4*)&halo[s][c0];
            float hl = __shfl_up_sync(0xffffffffu, hv.w, 1, 16);
            float hr = __shfl_down_sync(0xffffffffu, hv.x, 1, 16);
            if (seg == 0)  hl = 0.f;
            if (seg == 15) hr = 0.f;
            Hh[0] = fmaf(W1, hl,   fmaf(W1, hv.y, hv.x));
            Hh[1] = fmaf(W1, hv.x, fmaf(W1, hv.z, hv.y));
            Hh[2] = fmaf(W1, hv.y, fmaf(W1, hv.w, hv.z));
            Hh[3] = fmaf(W1, hv.z, fmaf(W1, hr,   hv.w));
        }
        if (do_wait) pha[s] ^= 1;
        __syncthreads();

        float4 u4 = *(const float4*)&HS[s][2 * band][c0];       // H(row-1)
        float4 d4 = *(const float4*)&HS[s][2 * band + 3][c0];   // H(row+2)
        if (band == bband) {
            const float4 h4 = make_float4(Hh[0], Hh[1], Hh[2], Hh[3]);
            if (rank == 0) d4 = h4; else u4 = h4;
        }
        const float up[4] = {u4.x, u4.y, u4.z, u4.w};
        const float dn[4] = {d4.x, d4.y, d4.z, d4.w};
#pragma unroll
        for (int j = 0; j < 4; ++j) {
            const float s0 = fmaf(W1, up[j] + H1[j], H0[j] + EPS);
            const float s1 = fmaf(W1, H0[j] + dn[j], H1[j] + EPS);
            o[0][j] = __fdividef(tg[0][j], s0);
            o[1][j] = __fdividef(tg[1][j], s1);
        }

        // send my boundary out-row to peer's halo slot for the NEXT halfstep
        if (band == bband) {
            const float* orow = o[rank ? 0 : 1];
            asm volatile("st.shared::cluster.v4.f32 [%0], {%1, %2, %3, %4};"
                         :: "r"(rhalo[s ^ 1]),
                            "f"(orow[0]), "f"(orow[1]), "f"(orow[2]), "f"(orow[3])
                         : "memory");
            asm volatile("mbarrier.arrive.release.cluster.shared::cluster.b64 _, [%0];"
                         :: "r"(rmb[s ^ 1]) : "memory");
        }
    };

    for (int it = 0; it < ITERS; ++it) {
        halfstep(v, b, u, 0, it > 0);   // h even: v = b/(Ku)
        halfstep(u, a, v, 1, true);     // h odd : u = a/(Kv)
    }

    // ---- cost = u . (Mv),  Mv = Hg(v) + W1*(T[r-1]+T[r+1]),  T = v + 2*Hg(v)
    float HG0[4], HG1[4], T0[4], T1[4];
    {
        float lf0 = __shfl_up_sync(0xffffffffu, v[0][3], 1, 16);
        float rt0 = __shfl_down_sync(0xffffffffu, v[0][0], 1, 16);
        float lf1 = __shfl_up_sync(0xffffffffu, v[1][3], 1, 16);
        float rt1 = __shfl_down_sync(0xffffffffu, v[1][0], 1, 16);
        if (seg == 0)  { lf0 = 0.f; lf1 = 0.f; }
        if (seg == 15) { rt0 = 0.f; rt1 = 0.f; }
        HG0[0] = W1 * (lf0 + v[0][1]);     HG1[0] = W1 * (lf1 + v[1][1]);
        HG0[1] = W1 * (v[0][0] + v[0][2]); HG1[1] = W1 * (v[1][0] + v[1][2]);
        HG0[2] = W1 * (v[0][1] + v[0][3]); HG1[2] = W1 * (v[1][1] + v[1][3]);
        HG0[3] = W1 * (v[0][2] + rt0);     HG1[3] = W1 * (v[1][2] + rt1);
#pragma unroll
        for (int j = 0; j < 4; ++j) {
            T0[j] = fmaf(2.f, HG0[j], v[0][j]);
            T1[j] = fmaf(2.f, HG1[j], v[1][j]);
        }
    }
    *(float4*)&HS[0][2 * band + 1][c0] = make_float4(T0[0], T0[1], T0[2], T0[3]);
    *(float4*)&HS[0][2 * band + 2][c0] = make_float4(T1[0], T1[1], T1[2], T1[3]);

    // T of the remote halo row: v-halo still valid in slot 1 (sent end of h=98)
    float Th[4] = {0.f, 0.f, 0.f, 0.f};
    if (wid == bwarp) {
        const float4 hv = *(const float4*)&halo[1][c0];
        float hl = __shfl_up_sync(0xffffffffu, hv.w, 1, 16);
        float hr = __shfl_down_sync(0xffffffffu, hv.x, 1, 16);
        if (seg == 0)  hl = 0.f;
        if (seg == 15) hr = 0.f;
        Th[0] = fmaf(2.f * W1, hl + hv.y,   hv.x);
        Th[1] = fmaf(2.f * W1, hv.x + hv.z, hv.y);
        Th[2] = fmaf(2.f * W1, hv.y + hv.w, hv.z);
        Th[3] = fmaf(2.f * W1, hv.z + hr,   hv.w);
    }
    __syncthreads();

    float4 u4 = *(const float4*)&HS[0][2 * band][c0];
    float4 d4 = *(const float4*)&HS[0][2 * band + 3][c0];
    if (band == bband) {
        const float4 h4 = make_float4(Th[0], Th[1], Th[2], Th[3]);
        if (rank == 0) d4 = h4; else u4 = h4;
    }
    const float up[4] = {u4.x, u4.y, u4.z, u4.w};
    const float dn[4] = {d4.x, d4.y, d4.z, d4.w};

    float local = 0.f;
#pragma unroll
    for (int j = 0; j < 4; ++j) {
        const float mv0 = fmaf(W1, up[j] + T1[j], HG0[j]);
        const float mv1 = fmaf(W1, T0[j] + dn[j], HG1[j]);
        local = fmaf(u[0][j], mv0, fmaf(u[1][j], mv1, local));
    }
    const float cost = blockReduceSum256(local, red);

    // no CTA may exit while the peer could still write our smem
    asm volatile("barrier.cluster.arrive.aligned;" ::: "memory");
    asm volatile("barrier.cluster.wait.aligned;"   ::: "memory");

    if (t == 0) {
        const bool valid = (asumT > 0.5f) && (bsumT > 0.5f);
        g_costs[blockIdx.x] = valid ? cost : 0.f;
        __threadfence();
        const int prev = atomicAdd(&g_done, 1);
        if (prev == 2 * NBATCH - 1) {
            g_done = 0;
            __threadfence();
            float s = 0.f;
#pragma unroll
            for (int i = 0; i < 2 * NBATCH; i += 2) s += g_costs[i] + g_costs[i + 1];
            out[0] = s * (1.f / (float)NBATCH);
        }
    }
}

extern "C" void kernel_launch(void* const* d_in, const int* in_sizes, int n_in,
                              void* d_out, int out_size) {
    (void)in_sizes; (void)n_in; (void)out_size;
    const float* pred = (const float*)d_in[0];
    const float* gt   = (const float*)d_in[1];
    pool_kernel<<<512, 256>>>(pred, gt);
    sinkhorn_kernel<<<NBATCH * 2, 256>>>((float*)d_out);
}

// round 6
// speedup vs baseline: 1.0294x; 1.0294x over previous
#include <cuda_runtime.h>

// Sinkhorn OT loss on 64x64 pooled grids, 2-CTA cluster per batch.
// K = exp(-C/0.1): exact (to fp32) as two 3-tap separable passes, W1=exp(-10).
// Each CTA owns 32 rows; the single cross-CTA halo row per halfstep travels via
// st.shared::cluster + remote mbarrier arrive. R6 FIX vs R5: the mbarrier wait
// now sits AFTER __syncthreads, so only the boundary warp stalls on the DSMEM
// round-trip while the other 7 warps run ahead into the next halfstep's
// H-phase -- the cluster latency overlaps with local compute instead of
// serializing all warps at the block barrier every halfstep.

#define NBATCH 16
#define ITERS  50
#define EPS    1e-8f
#define W1     4.5399929762484854e-05f   // exp(-10)

__device__ float g_pooled[2][NBATCH][4096];
__device__ float g_costs[NBATCH * 2];
__device__ int   g_done;

// ---------------------------------------------------------------- pooling
__global__ __launch_bounds__(256) void pool_kernel(const float* __restrict__ pred,
                                                   const float* __restrict__ gt) {
    const int bid    = blockIdx.x;          // 0..511
    const int tensor = bid >> 8;
    const int batch  = (bid >> 4) & 15;
    const int rb     = bid & 15;
    const float* src = (tensor ? gt : pred) + (size_t)batch * 262144;

    const int pr = rb * 4 + (threadIdx.x >> 6);
    const int pc = threadIdx.x & 63;
    const float4* p = (const float4*)(src + (size_t)pr * 4096 + pc * 8);

    float s = 0.f;
#pragma unroll
    for (int y = 0; y < 8; ++y) {
        float4 v0 = p[y * 128];
        float4 v1 = p[y * 128 + 1];
        s += (v0.x + v0.y) + (v0.z + v0.w) + (v1.x + v1.y) + (v1.z + v1.w);
    }
    g_pooled[tensor][batch][pr * 64 + pc] = s;
}

// ---------------------------------------------------------------- helpers
__device__ __forceinline__ unsigned smem_u32(const void* p) {
    unsigned a;
    asm("{ .reg .u64 t; cvta.to.shared.u64 t, %1; cvt.u32.u64 %0, t; }"
        : "=r"(a) : "l"(p));
    return a;
}
__device__ __forceinline__ unsigned mapa_u32(unsigned addr, unsigned rank) {
    unsigned r;
    asm("mapa.shared::cluster.u32 %0, %1, %2;" : "=r"(r) : "r"(addr), "r"(rank));
    return r;
}
__device__ __forceinline__ void mbar_wait_acq_cluster(unsigned mb, unsigned parity) {
    asm volatile(
        "{\n\t"
        ".reg .pred P;\n"
        "W_%=:\n\t"
        "mbarrier.try_wait.parity.acquire.cluster.shared::cta.b64 P, [%0], %1;\n\t"
        "@!P bra W_%=;\n\t"
        "}" :: "r"(mb), "r"(parity) : "memory");
}

__device__ __forceinline__ float blockReduceSum256(float val, float* red) {
#pragma unroll
    for (int o = 16; o; o >>= 1) val += __shfl_xor_sync(0xffffffffu, val, o);
    const int w = threadIdx.x >> 5, l = threadIdx.x & 31;
    __syncthreads();
    if (l == 0) red[w] = val;
    __syncthreads();
    float s = ((red[0] + red[1]) + (red[2] + red[3]))
            + ((red[4] + red[5]) + (red[6] + red[7]));
    __syncthreads();
    return s;
}

// ---------------------------------------------------------------- sinkhorn
__global__ __launch_bounds__(256, 1) __cluster_dims__(2, 1, 1)
void sinkhorn_kernel(float* __restrict__ out) {
    __shared__ __align__(16) float HS[2][34][64];   // H field, double-buffered; rows 0,33 = 0 pads
    __shared__ __align__(16) float halo[2][64];     // peer-written input-halo rows, per-slot
    __shared__ float red[8];
    __shared__ float xpart[2];
    __shared__ unsigned long long mbar[2];

    const int t     = threadIdx.x;
    const int wid   = t >> 5, l = t & 31;
    const int seg   = l & 15;
    const int band  = 2 * wid + (l >> 4);   // 0..15, 2 local rows each
    const int c0    = seg * 4;
    const int rank  = blockIdx.x & 1;       // == cluster_ctarank for 1-D cluster
    const int batch = blockIdx.x >> 1;
    const int bband = rank ? 0 : 15;        // band adjacent to the other CTA
    const int bwarp = rank ? 0 : 7;
    const unsigned peer = rank ^ 1;

    if (t == 0) {
        asm volatile("mbarrier.init.shared.b64 [%0], %1;"
                     :: "r"(smem_u32(&mbar[0])), "r"(16) : "memory");
        asm volatile("mbarrier.init.shared.b64 [%0], %1;"
                     :: "r"(smem_u32(&mbar[1])), "r"(16) : "memory");
    }
    for (int i = t; i < 2 * 34 * 64; i += 256) ((float*)HS)[i] = 0.f;  // zero pads
    if (t < 64) halo[0][t] = 1.f;   // initial u == 1 on the remote halo row

    const unsigned mb0 = smem_u32(&mbar[0]);
    const unsigned mb1 = smem_u32(&mbar[1]);
    const unsigned rmb[2]   = { mapa_u32(mb0, peer), mapa_u32(mb1, peer) };
    const unsigned rhalo[2] = { mapa_u32(smem_u32(&halo[0][0]), peer) + (unsigned)c0 * 4u,
                                mapa_u32(smem_u32(&halo[1][0]), peer) + (unsigned)c0 * 4u };

    // ---- load my half of the pooled grids (global rows rank*32 .. +31) ----
    float a[2][4], b[2][4], u[2][4], v[2][4];
    float asum = 0.f, bsum = 0.f;
    {
        const float* pa = &g_pooled[0][batch][(rank * 32 + band * 2) * 64 + c0];
        const float* pb = &g_pooled[1][batch][(rank * 32 + band * 2) * 64 + c0];
#pragma unroll
        for (int i = 0; i < 2; ++i) {
            const float4 x = *(const float4*)(pa + i * 64);
            const float4 y = *(const float4*)(pb + i * 64);
            a[i][0] = x.x; a[i][1] = x.y; a[i][2] = x.z; a[i][3] = x.w;
            b[i][0] = y.x; b[i][1] = y.y; b[i][2] = y.z; b[i][3] = y.w;
            asum += (x.x + x.y) + (x.z + x.w);
            bsum += (y.x + y.y) + (y.z + y.w);
        }
    }
    asum = blockReduceSum256(asum, red);
    bsum = blockReduceSum256(bsum, red);

    // cross-CTA partial-sum exchange (one-time)
    if (t == 0) {
        const unsigned rxp = mapa_u32(smem_u32(&xpart[0]), peer);
        asm volatile("st.shared::cluster.f32 [%0], %1;" :: "r"(rxp),      "f"(asum) : "memory");
        asm volatile("st.shared::cluster.f32 [%0], %1;" :: "r"(rxp + 4u), "f"(bsum) : "memory");
    }
    asm volatile("barrier.cluster.arrive.aligned;" ::: "memory");
    asm volatile("barrier.cluster.wait.aligned;"   ::: "memory");

    // canonical rank0+rank1 order -> both CTAs get bitwise-identical totals
    const float at0 = rank ? xpart[0] : asum;
    const float at1 = rank ? asum     : xpart[0];
    const float bt0 = rank ? xpart[1] : bsum;
    const float bt1 = rank ? bsum     : xpart[1];
    const float asumT = at0 + at1;
    const float bsumT = bt0 + bt1;
    const float ra  = 1.f / fmaxf(asumT, 1e-8f);
    const float rbv = 1.f / fmaxf(bsumT, 1e-8f);
#pragma unroll
    for (int i = 0; i < 2; ++i)
#pragma unroll
        for (int j = 0; j < 4; ++j) {
            a[i][j] *= ra; b[i][j] *= rbv; u[i][j] = 1.f;
        }

    int pha[2] = {0, 0};

    // out = tgt / (Ve(He(in)) + eps); slot s doubles as HS buffer index.
    auto halfstep = [&](float (&o)[2][4], const float (&tg)[2][4],
                        const float (&in)[2][4], const int s, const bool do_wait) {
        float H0[4], H1[4];
        {
            float lf0 = __shfl_up_sync(0xffffffffu, in[0][3], 1, 16);
            float rt0 = __shfl_down_sync(0xffffffffu, in[0][0], 1, 16);
            float lf1 = __shfl_up_sync(0xffffffffu, in[1][3], 1, 16);
            float rt1 = __shfl_down_sync(0xffffffffu, in[1][0], 1, 16);
            if (seg == 0)  { lf0 = 0.f; lf1 = 0.f; }
            if (seg == 15) { rt0 = 0.f; rt1 = 0.f; }
            H0[0] = fmaf(W1, lf0,      fmaf(W1, in[0][1], in[0][0]));
            H0[1] = fmaf(W1, in[0][0], fmaf(W1, in[0][2], in[0][1]));
            H0[2] = fmaf(W1, in[0][1], fmaf(W1, in[0][3], in[0][2]));
            H0[3] = fmaf(W1, in[0][2], fmaf(W1, rt0,      in[0][3]));
            H1[0] = fmaf(W1, lf1,      fmaf(W1, in[1][1], in[1][0]));
            H1[1] = fmaf(W1, in[1][0], fmaf(W1, in[1][2], in[1][1]));
            H1[2] = fmaf(W1, in[1][1], fmaf(W1, in[1][3], in[1][2]));
            H1[3] = fmaf(W1, in[1][2], fmaf(W1, rt1,      in[1][3]));
        }
        *(float4*)&HS[s][2 * band + 1][c0] = make_float4(H0[0], H0[1], H0[2], H0[3]);
        *(float4*)&HS[s][2 * band + 2][c0] = make_float4(H1[0], H1[1], H1[2], H1[3]);
        __syncthreads();

        float4 u4 = *(const float4*)&HS[s][2 * band][c0];       // H(row-1)
        float4 d4 = *(const float4*)&HS[s][2 * band + 3][c0];   // H(row+2)

        // R6 FIX: wait AFTER the block barrier -- only this warp stalls on the
        // cluster round-trip; the other 7 warps run ahead to the next BAR.
        float Hh[4] = {0.f, 0.f, 0.f, 0.f};
        if (wid == bwarp) {
            if (do_wait) mbar_wait_acq_cluster(s ? mb1 : mb0, (unsigned)pha[s]);
            const float4 hv = *(const float4*)&halo[s][c0];
            float hl = __shfl_up_sync(0xffffffffu, hv.w, 1, 16);
            float hr = __shfl_down_sync(0xffffffffu, hv.x, 1, 16);
            if (seg == 0)  hl = 0.f;
            if (seg == 15) hr = 0.f;
            Hh[0] = fmaf(W1, hl,   fmaf(W1, hv.y, hv.x));
            Hh[1] = fmaf(W1, hv.x, fmaf(W1, hv.z, hv.y));
            Hh[2] = fmaf(W1, hv.y, fmaf(W1, hv.w, hv.z));
            Hh[3] = fmaf(W1, hv.z, fmaf(W1, hr,   hv.w));
        }
        if (do_wait) pha[s] ^= 1;

        if (band == bband) {
            const float4 h4 = make_float4(Hh[0], Hh[1], Hh[2], Hh[3]);
            if (rank == 0) d4 = h4; else u4 = h4;
        }
        const float up[4] = {u4.x, u4.y, u4.z, u4.w};
        const float dn[4] = {d4.x, d4.y, d4.z, d4.w};
#pragma unroll
        for (int j = 0; j < 4; ++j) {
            const float s0 = fmaf(W1, up[j] + H1[j], H0[j] + EPS);
            const float s1 = fmaf(W1, H0[j] + dn[j], H1[j] + EPS);
            o[0][j] = __fdividef(tg[0][j], s0);
            o[1][j] = __fdividef(tg[1][j], s1);
        }

        // send my boundary out-row to peer's halo slot for the NEXT halfstep
        if (band == bband) {
            const float* orow = o[rank ? 0 : 1];
            asm volatile("st.shared::cluster.v4.f32 [%0], {%1, %2, %3, %4};"
                         :: "r"(rhalo[s ^ 1]),
                            "f"(orow[0]), "f"(orow[1]), "f"(orow[2]), "f"(orow[3])
                         : "memory");
            asm volatile("mbarrier.arrive.release.cluster.shared::cluster.b64 _, [%0];"
                         :: "r"(rmb[s ^ 1]) : "memory");
        }
    };

    for (int it = 0; it < ITERS; ++it) {
        halfstep(v, b, u, 0, it > 0);   // h even: v = b/(Ku)
        halfstep(u, a, v, 1, true);     // h odd : u = a/(Kv)
    }

    // ---- cost = u . (Mv),  Mv = Hg(v) + W1*(T[r-1]+T[r+1]),  T = v + 2*Hg(v)
    float HG0[4], HG1[4], T0[4], T1[4];
    {
        float lf0 = __shfl_up_sync(0xffffffffu, v[0][3], 1, 16);
        float rt0 = __shfl_down_sync(0xffffffffu, v[0][0], 1, 16);
        float lf1 = __shfl_up_sync(0xffffffffu, v[1][3], 1, 16);
        float rt1 = __shfl_down_sync(0xffffffffu, v[1][0], 1, 16);
        if (seg == 0)  { lf0 = 0.f; lf1 = 0.f; }
        if (seg == 15) { rt0 = 0.f; rt1 = 0.f; }
        HG0[0] = W1 * (lf0 + v[0][1]);     HG1[0] = W1 * (lf1 + v[1][1]);
        HG0[1] = W1 * (v[0][0] + v[0][2]); HG1[1] = W1 * (v[1][0] + v[1][2]);
        HG0[2] = W1 * (v[0][1] + v[0][3]); HG1[2] = W1 * (v[1][1] + v[1][3]);
        HG0[3] = W1 * (v[0][2] + rt0);     HG1[3] = W1 * (v[1][2] + rt1);
#pragma unroll
        for (int j = 0; j < 4; ++j) {
            T0[j] = fmaf(2.f, HG0[j], v[0][j]);
            T1[j] = fmaf(2.f, HG1[j], v[1][j]);
        }
    }
    *(float4*)&HS[0][2 * band + 1][c0] = make_float4(T0[0], T0[1], T0[2], T0[3]);
    *(float4*)&HS[0][2 * band + 2][c0] = make_float4(T1[0], T1[1], T1[2], T1[3]);

    // T of the remote halo row: v-halo still valid in slot 1 (sent end of h=98)
    float Th[4] = {0.f, 0.f, 0.f, 0.f};
    if (wid == bwarp) {
        const float4 hv = *(const float4*)&halo[1][c0];
        float hl = __shfl_up_sync(0xffffffffu, hv.w, 1, 16);
        float hr = __shfl_down_sync(0xffffffffu, hv.x, 1, 16);
        if (seg == 0)  hl = 0.f;
        if (seg == 15) hr = 0.f;
        Th[0] = fmaf(2.f * W1, hl + hv.y,   hv.x);
        Th[1] = fmaf(2.f * W1, hv.x + hv.z, hv.y);
        Th[2] = fmaf(2.f * W1, hv.y + hv.w, hv.z);
        Th[3] = fmaf(2.f * W1, hv.z + hr,   hv.w);
    }
    __syncthreads();

    float4 u4 = *(const float4*)&HS[0][2 * band][c0];
    float4 d4 = *(const float4*)&HS[0][2 * band + 3][c0];
    if (band == bband) {
        const float4 h4 = make_float4(Th[0], Th[1], Th[2], Th[3]);
        if (rank == 0) d4 = h4; else u4 = h4;
    }
    const float up[4] = {u4.x, u4.y, u4.z, u4.w};
    const float dn[4] = {d4.x, d4.y, d4.z, d4.w};

    float local = 0.f;
#pragma unroll
    for (int j = 0; j < 4; ++j) {
        const float mv0 = fmaf(W1, up[j] + T1[j], HG0[j]);
        const float mv1 = fmaf(W1, T0[j] + dn[j], HG1[j]);
        local = fmaf(u[0][j], mv0, fmaf(u[1][j], mv1, local));
    }
    const float cost = blockReduceSum256(local, red);

    // no CTA may exit while the peer could still write our smem
    asm volatile("barrier.cluster.arrive.aligned;" ::: "memory");
    asm volatile("barrier.cluster.wait.aligned;"   ::: "memory");

    if (t == 0) {
        const bool valid = (asumT > 0.5f) && (bsumT > 0.5f);
        g_costs[blockIdx.x] = valid ? cost : 0.f;
        __threadfence();
        const int prev = atomicAdd(&g_done, 1);
        if (prev == 2 * NBATCH - 1) {
            g_done = 0;
            __threadfence();
            float s = 0.f;
#pragma unroll
            for (int i = 0; i < 2 * NBATCH; i += 2) s += g_costs[i] + g_costs[i + 1];
            out[0] = s * (1.f / (float)NBATCH);
        }
    }
}

extern "C" void kernel_launch(void* const* d_in, const int* in_sizes, int n_in,
                              void* d_out, int out_size) {
    (void)in_sizes; (void)n_in; (void)out_size;
    const float* pred = (const float*)d_in[0];
    const float* gt   = (const float*)d_in[1];
    pool_kernel<<<512, 256>>>(pred, gt);
    sinkhorn_kernel<<<NBATCH * 2, 256>>>((float*)d_out);
}

// round 7
// speedup vs baseline: 1.6121x; 1.5661x over previous
#include <cuda_runtime.h>

// Sinkhorn OT loss on 64x64 pooled grids. K = exp(-C/0.1) is exact (to fp32)
// as two 3-tap separable passes, W1 = exp(-10).
// R7: single CTA per batch, but NO block-wide barrier in the loop. Each warp
// owns 8 contiguous rows (2 half-warp bands x 4 rows): vertical neighbors are
// in-register except the band seam (1 shfl.xor) and the warp seams (1 STS.128
// + 1 LDS.128, ordered by per-pair named barriers bar.sync id,64). Warps form
// a loose wavefront instead of locking step at __syncthreads -> per-warp
// latency jitter no longer accumulates into a block-wide period.

#define NBATCH 16
#define ITERS  50
#define EPS    1e-8f
#define W1     4.5399929762484854e-05f   // exp(-10)

__device__ float g_pooled[2][NBATCH][4096];
__device__ float g_costs[NBATCH];
__device__ int   g_done;

// ---------------------------------------------------------------- pooling
__global__ __launch_bounds__(256) void pool_kernel(const float* __restrict__ pred,
                                                   const float* __restrict__ gt) {
    const int bid    = blockIdx.x;          // 0..511
    const int tensor = bid >> 8;
    const int batch  = (bid >> 4) & 15;
    const int rb     = bid & 15;
    const float* src = (tensor ? gt : pred) + (size_t)batch * 262144;

    const int pr = rb * 4 + (threadIdx.x >> 6);
    const int pc = threadIdx.x & 63;
    const float4* p = (const float4*)(src + (size_t)pr * 4096 + pc * 8);

    float s = 0.f;
#pragma unroll
    for (int y = 0; y < 8; ++y) {
        float4 v0 = p[y * 128];
        float4 v1 = p[y * 128 + 1];
        s += (v0.x + v0.y) + (v0.z + v0.w) + (v1.x + v1.y) + (v1.z + v1.w);
    }
    g_pooled[tensor][batch][pr * 64 + pc] = s;
}

// ---------------------------------------------------------------- helpers
#define NBAR(id) asm volatile("bar.sync %0, 64;" :: "r"(id) : "memory")

__device__ __forceinline__ float blockReduceSum256(float val, float* red) {
#pragma unroll
    for (int o = 16; o; o >>= 1) val += __shfl_xor_sync(0xffffffffu, val, o);
    const int w = threadIdx.x >> 5, l = threadIdx.x & 31;
    __syncthreads();
    if (l == 0) red[w] = val;
    __syncthreads();
    float s = ((red[0] + red[1]) + (red[2] + red[3]))
            + ((red[4] + red[5]) + (red[6] + red[7]));
    __syncthreads();
    return s;
}

// ---------------------------------------------------------------- sinkhorn
__global__ __launch_bounds__(256, 1) void sinkhorn_kernel(float* __restrict__ out) {
    // [parity][warp-slot][col]; slot w+1 written by warp w; slots 0 and 9 = 0 pads
    __shared__ __align__(16) float TOPB[2][10][64];   // each warp's H row 8w
    __shared__ __align__(16) float BOTB[2][10][64];   // each warp's H row 8w+7
    __shared__ float red[8];

    const int t    = threadIdx.x;
    const int w    = t >> 5, l = t & 31;
    const int seg  = l & 15;
    const int c0   = seg * 4;
    const int lowb = l >> 4;             // 0: rows 8w..8w+3, 1: rows 8w+4..8w+7
    const int bid  = blockIdx.x;
    const int r0   = w * 8 + lowb * 4;   // first grid row of this thread

    if (t < 64) {
        TOPB[0][9][t] = 0.f; TOPB[1][9][t] = 0.f;   // below grid (warp7 band1 load)
        BOTB[0][0][t] = 0.f; BOTB[1][0][t] = 0.f;   // above grid (warp0 band0 load)
    }

    // exchange pointers (parity 0); +640 floats = parity 1
    float*       stp = lowb ? &BOTB[0][w + 1][c0] : &TOPB[0][w + 1][c0];
    const float* ldp = lowb ? &TOPB[0][w + 2][c0] : &BOTB[0][w][c0];

    // ---- load pooled grids, normalize ----
    float a[4][4], b[4][4], u[4][4], v[4][4];
    float asum = 0.f, bsum = 0.f;
    {
        const float* pa = &g_pooled[0][bid][r0 * 64 + c0];
        const float* pb = &g_pooled[1][bid][r0 * 64 + c0];
#pragma unroll
        for (int i = 0; i < 4; ++i) {
            const float4 x = *(const float4*)(pa + i * 64);
            const float4 y = *(const float4*)(pb + i * 64);
            a[i][0] = x.x; a[i][1] = x.y; a[i][2] = x.z; a[i][3] = x.w;
            b[i][0] = y.x; b[i][1] = y.y; b[i][2] = y.z; b[i][3] = y.w;
            asum += (x.x + x.y) + (x.z + x.w);
            bsum += (y.x + y.y) + (y.z + y.w);
        }
    }
    asum = blockReduceSum256(asum, red);   // __syncthreads inside also fences pad init
    bsum = blockReduceSum256(bsum, red);
    const float ra  = 1.f / fmaxf(asum, 1e-8f);
    const float rbv = 1.f / fmaxf(bsum, 1e-8f);
#pragma unroll
    for (int i = 0; i < 4; ++i)
#pragma unroll
        for (int j = 0; j < 4; ++j) {
            a[i][j] *= ra; b[i][j] *= rbv; u[i][j] = 1.f;
        }

    // out = tgt / (Ve(He(in)) + eps). All exchanges are intra-halfstep; parity
    // double-buffers the warp-seam rows against h/h+2 slot reuse.
    auto halfstep = [&](float (&o)[4][4], const float (&tg)[4][4],
                        const float (&in)[4][4], const int par) {
        float H[4][4];
#pragma unroll
        for (int i = 0; i < 4; ++i) {
            float lf = __shfl_up_sync(0xffffffffu, in[i][3], 1, 16);
            float rt = __shfl_down_sync(0xffffffffu, in[i][0], 1, 16);
            if (seg == 0)  lf = 0.f;
            if (seg == 15) rt = 0.f;
            H[i][0] = fmaf(W1, lf + in[i][1],       in[i][0]);
            H[i][1] = fmaf(W1, in[i][0] + in[i][2], in[i][1]);
            H[i][2] = fmaf(W1, in[i][1] + in[i][3], in[i][2]);
            H[i][3] = fmaf(W1, in[i][2] + rt,       in[i][3]);
        }
        // band seam (rows 8w+3 <-> 8w+4) via xor-16 shuffle, no smem
        float xb[4];
#pragma unroll
        for (int j = 0; j < 4; ++j) {
            const float s = lowb ? H[0][j] : H[3][j];
            xb[j] = __shfl_xor_sync(0xffffffffu, s, 16);
        }
        // warp seam rows through smem, pairwise-ordered
        const float4 sv = lowb ? make_float4(H[3][0], H[3][1], H[3][2], H[3][3])
                               : make_float4(H[0][0], H[0][1], H[0][2], H[0][3]);
        *(float4*)(stp + par * 640) = sv;
        if (w > 0) NBAR(w);          // with warp w-1
        if (w < 7) NBAR(w + 1);      // with warp w+1
        const float4 nb = *(const float4*)(ldp + par * 640);

        float up[4], dn[4];
        up[0] = lowb ? xb[0] : nb.x;  dn[0] = lowb ? nb.x : xb[0];
        up[1] = lowb ? xb[1] : nb.y;  dn[1] = lowb ? nb.y : xb[1];
        up[2] = lowb ? xb[2] : nb.z;  dn[2] = lowb ? nb.z : xb[2];
        up[3] = lowb ? xb[3] : nb.w;  dn[3] = lowb ? nb.w : xb[3];

#pragma unroll
        for (int i = 0; i < 4; ++i) {
#pragma unroll
            for (int j = 0; j < 4; ++j) {
                const float nu = (i == 0) ? up[j] : H[i - 1][j];
                const float nd = (i == 3) ? dn[j] : H[i + 1][j];
                const float den = fmaf(W1, nu + nd, H[i][j] + EPS);
                o[i][j] = __fdividef(tg[i][j], den);
            }
        }
    };

    for (int it = 0; it < ITERS; ++it) {
        halfstep(v, b, u, 0);
        halfstep(u, a, v, 1);
    }

    // ---- cost = u.(Mv); Mv = Hg(v) + W1*(T[r-1]+T[r+1]), T = v + 2*Hg(v) ----
    float HG[4][4], T[4][4];
#pragma unroll
    for (int i = 0; i < 4; ++i) {
        float lf = __shfl_up_sync(0xffffffffu, v[i][3], 1, 16);
        float rt = __shfl_down_sync(0xffffffffu, v[i][0], 1, 16);
        if (seg == 0)  lf = 0.f;
        if (seg == 15) rt = 0.f;
        HG[i][0] = W1 * (lf + v[i][1]);
        HG[i][1] = W1 * (v[i][0] + v[i][2]);
        HG[i][2] = W1 * (v[i][1] + v[i][3]);
        HG[i][3] = W1 * (v[i][2] + rt);
#pragma unroll
        for (int j = 0; j < 4; ++j) T[i][j] = fmaf(2.f, HG[i][j], v[i][j]);
    }
    float xb[4];
#pragma unroll
    for (int j = 0; j < 4; ++j) {
        const float s = lowb ? T[0][j] : T[3][j];
        xb[j] = __shfl_xor_sync(0xffffffffu, s, 16);
    }
    const float4 sv = lowb ? make_float4(T[3][0], T[3][1], T[3][2], T[3][3])
                           : make_float4(T[0][0], T[0][1], T[0][2], T[0][3]);
    *(float4*)stp = sv;                    // parity 0; prior readers fenced by h=99 bars
    if (w > 0) NBAR(w);
    if (w < 7) NBAR(w + 1);
    const float4 nb = *(const float4*)ldp;

    float up[4], dn[4];
    up[0] = lowb ? xb[0] : nb.x;  dn[0] = lowb ? nb.x : xb[0];
    up[1] = lowb ? xb[1] : nb.y;  dn[1] = lowb ? nb.y : xb[1];
    up[2] = lowb ? xb[2] : nb.z;  dn[2] = lowb ? nb.z : xb[2];
    up[3] = lowb ? xb[3] : nb.w;  dn[3] = lowb ? nb.w : xb[3];

    float local = 0.f;
#pragma unroll
    for (int i = 0; i < 4; ++i) {
#pragma unroll
        for (int j = 0; j < 4; ++j) {
            const float tu = (i == 0) ? up[j] : T[i - 1][j];
            const float td = (i == 3) ? dn[j] : T[i + 1][j];
            const float mv = fmaf(W1, tu + td, HG[i][j]);
            local = fmaf(u[i][j], mv, local);
        }
    }
    const float cost = blockReduceSum256(local, red);

    if (t == 0) {
        const bool valid = (asum > 0.5f) && (bsum > 0.5f);
        g_costs[bid] = valid ? cost : 0.f;
        __threadfence();
        const int prev = atomicAdd(&g_done, 1);
        if (prev == NBATCH - 1) {
            g_done = 0;
            __threadfence();
            float s = 0.f;
#pragma unroll
            for (int i = 0; i < NBATCH; ++i) s += g_costs[i];
            out[0] = s * (1.f / (float)NBATCH);
        }
    }
}

extern "C" void kernel_launch(void* const* d_in, const int* in_sizes, int n_in,
                              void* d_out, int out_size) {
    (void)in_sizes; (void)n_in; (void)out_size;
    const float* pred = (const float*)d_in[0];
    const float* gt   = (const float*)d_in[1];
    pool_kernel<<<512, 256>>>(pred, gt);
    sinkhorn_kernel<<<NBATCH, 256>>>((float*)d_out);
}

// round 8
// speedup vs baseline: 1.7129x; 1.0626x over previous
#include <cuda_runtime.h>

// Sinkhorn OT loss on 64x64 pooled grids. K = exp(-C/0.1) is exact (to fp32)
// as two 3-tap separable passes, W1 = exp(-10).
// R8: the loop is ISSUE-SLOT bound (~420 instr/SMSP/halfstep vs MUFU floor
// 256 cyc). V-phase arithmetic is packed into f32x2 (add/mul/fma.rn.f32x2) --
// all V operands are whole register-pairs, so packing is register-allocation
// free. H-phase stays scalar (horizontal shifts are cross-pair; packing there
// costs MOVs) with W1 as FFMA immediate (rt=1). R2 sync skeleton (one
// __syncthreads per halfstep, double-buffered seam rows) unchanged.

typedef unsigned long long u64;

#define NBATCH 16
#define ITERS  50
#define EPS    1e-8f
#define W1     4.5399929762484854e-05f   // exp(-10)

__device__ float g_pooled[2][NBATCH][4096];
__device__ float g_costs[NBATCH];
__device__ int   g_done;

// ---------------------------------------------------------------- f32x2
__device__ __forceinline__ u64 PK(float lo, float hi) {
    u64 r; asm("mov.b64 %0, {%1, %2};" : "=l"(r) : "f"(lo), "f"(hi)); return r;
}
__device__ __forceinline__ void UPK(float& lo, float& hi, u64 p) {
    asm("mov.b64 {%0, %1}, %2;" : "=f"(lo), "=f"(hi) : "l"(p));
}
__device__ __forceinline__ u64 ADD2(u64 a, u64 b) {
    u64 r; asm("add.rn.f32x2 %0, %1, %2;" : "=l"(r) : "l"(a), "l"(b)); return r;
}
__device__ __forceinline__ u64 MUL2(u64 a, u64 b) {
    u64 r; asm("mul.rn.f32x2 %0, %1, %2;" : "=l"(r) : "l"(a), "l"(b)); return r;
}
__device__ __forceinline__ u64 FMA2(u64 a, u64 b, u64 c) {
    u64 r; asm("fma.rn.f32x2 %0, %1, %2, %3;" : "=l"(r) : "l"(a), "l"(b), "l"(c)); return r;
}
__device__ __forceinline__ float RCPA(float x) {
    float r; asm("rcp.approx.f32 %0, %1;" : "=f"(r) : "f"(x)); return r;
}

// ---------------------------------------------------------------- pooling
__global__ __launch_bounds__(256) void pool_kernel(const float* __restrict__ pred,
                                                   const float* __restrict__ gt) {
    const int bid    = blockIdx.x;          // 0..511
    const int tensor = bid >> 8;
    const int batch  = (bid >> 4) & 15;
    const int rb     = bid & 15;
    const float* src = (tensor ? gt : pred) + (size_t)batch * 262144;

    const int pr = rb * 4 + (threadIdx.x >> 6);
    const int pc = threadIdx.x & 63;
    const float4* p = (const float4*)(src + (size_t)pr * 4096 + pc * 8);

    float s = 0.f;
#pragma unroll
    for (int y = 0; y < 8; ++y) {
        float4 v0 = p[y * 128];
        float4 v1 = p[y * 128 + 1];
        s += (v0.x + v0.y) + (v0.z + v0.w) + (v1.x + v1.y) + (v1.z + v1.w);
    }
    g_pooled[tensor][batch][pr * 64 + pc] = s;
}

// ---------------------------------------------------------------- sinkhorn
__device__ __forceinline__ float blockReduceSum256(float val, float* red) {
#pragma unroll
    for (int o = 16; o; o >>= 1) val += __shfl_xor_sync(0xffffffffu, val, o);
    const int w = threadIdx.x >> 5, l = threadIdx.x & 31;
    __syncthreads();
    if (l == 0) red[w] = val;
    __syncthreads();
    float s = ((red[0] + red[1]) + (red[2] + red[3]))
            + ((red[4] + red[5]) + (red[6] + red[7]));
    __syncthreads();
    return s;
}

__global__ __launch_bounds__(256, 1) void sinkhorn_kernel(float* __restrict__ out) {
    __shared__ __align__(16) float HT[2][18][64];  // seam: each band's H row 4b
    __shared__ __align__(16) float HB[2][18][64];  // seam: each band's H row 4b+3
    __shared__ float red[8];

    const int t    = threadIdx.x;
    const int w    = t >> 5, l = t & 31;
    const int seg  = l & 15;
    const int band = 2 * w + (l >> 4);   // 0..15, 4 rows each
    const int c0   = seg * 4;
    const int bid  = blockIdx.x;

    // zero everything once (rows 0 and 17 stay 0 = grid pads forever:
    // stores only ever hit rows 1..16)
    for (int i = t; i < 2 * 18 * 64; i += 256) {
        ((float*)HT)[i] = 0.f;
        ((float*)HB)[i] = 0.f;
    }

    const u64 W1x2 = PK(W1, W1);
    const u64 EPS2 = PK(EPS, EPS);

    // ---- load pooled grids, normalize, pack ----
    u64 a01[4], a23[4], b01[4], b23[4], u01[4], u23[4], v01[4], v23[4];
    float asum = 0.f, bsum = 0.f;
    float4 ax[4], bx[4];
    {
        const float* pa = &g_pooled[0][bid][(band * 4) * 64 + c0];
        const float* pb = &g_pooled[1][bid][(band * 4) * 64 + c0];
#pragma unroll
        for (int i = 0; i < 4; ++i) {
            ax[i] = *(const float4*)(pa + i * 64);
            bx[i] = *(const float4*)(pb + i * 64);
            asum += (ax[i].x + ax[i].y) + (ax[i].z + ax[i].w);
            bsum += (bx[i].x + bx[i].y) + (bx[i].z + bx[i].w);
        }
    }
    asum = blockReduceSum256(asum, red);   // internal syncthreads also fences pad zeroing
    bsum = blockReduceSum256(bsum, red);
    const float ra  = 1.f / fmaxf(asum, 1e-8f);
    const float rbv = 1.f / fmaxf(bsum, 1e-8f);
#pragma unroll
    for (int i = 0; i < 4; ++i) {
        a01[i] = PK(ax[i].x * ra,  ax[i].y * ra);
        a23[i] = PK(ax[i].z * ra,  ax[i].w * ra);
        b01[i] = PK(bx[i].x * rbv, bx[i].y * rbv);
        b23[i] = PK(bx[i].z * rbv, bx[i].w * rbv);
        u01[i] = PK(1.f, 1.f);
        u23[i] = PK(1.f, 1.f);
    }

    // out = tg / (Ve(He(in)) + eps). One __syncthreads per halfstep; seam rows
    // double-buffered by slot s (v-step: 0, u-step: 1).
    auto halfstep = [&](u64 (&o01)[4], u64 (&o23)[4],
                        const u64 (&tg01)[4], const u64 (&tg23)[4],
                        const u64 (&in01)[4], const u64 (&in23)[4], const int s) {
        // --- H phase: scalar (horizontal shifts are cross-pair) ---
        u64 H01[4], H23[4];
#pragma unroll
        for (int i = 0; i < 4; ++i) {
            float i0, i1, i2, i3;
            UPK(i0, i1, in01[i]);
            UPK(i2, i3, in23[i]);
            float lf = __shfl_up_sync(0xffffffffu, i3, 1, 16);
            float rt = __shfl_down_sync(0xffffffffu, i0, 1, 16);
            if (seg == 0)  lf = 0.f;
            if (seg == 15) rt = 0.f;
            const float h0 = fmaf(W1, lf + i1, i0);
            const float h1 = fmaf(W1, i0 + i2, i1);
            const float h2 = fmaf(W1, i1 + i3, i2);
            const float h3 = fmaf(W1, i2 + rt, i3);
            H01[i] = PK(h0, h1);   // dests allocatable into the pair: free
            H23[i] = PK(h2, h3);
        }
        *(ulonglong2*)&HT[s][band + 1][c0] = make_ulonglong2(H01[0], H23[0]);
        *(ulonglong2*)&HB[s][band + 1][c0] = make_ulonglong2(H01[3], H23[3]);
        __syncthreads();
        const ulonglong2 upv = *(const ulonglong2*)&HB[s][band][c0];      // H row 4b-1
        const ulonglong2 dnv = *(const ulonglong2*)&HT[s][band + 2][c0];  // H row 4b+4

        // --- V phase: packed f32x2 ---
#pragma unroll
        for (int i = 0; i < 4; ++i) {
            const u64 nu01 = (i == 0) ? upv.x : H01[i - 1];
            const u64 nu23 = (i == 0) ? upv.y : H23[i - 1];
            const u64 nd01 = (i == 3) ? dnv.x : H01[i + 1];
            const u64 nd23 = (i == 3) ? dnv.y : H23[i + 1];
            const u64 d01 = ADD2(FMA2(W1x2, ADD2(nu01, nd01), H01[i]), EPS2);
            const u64 d23 = ADD2(FMA2(W1x2, ADD2(nu23, nd23), H23[i]), EPS2);
            float d0, d1, d2, d3;
            UPK(d0, d1, d01);
            UPK(d2, d3, d23);
            o01[i] = MUL2(tg01[i], PK(RCPA(d0), RCPA(d1)));
            o23[i] = MUL2(tg23[i], PK(RCPA(d2), RCPA(d3)));
        }
    };

    for (int it = 0; it < ITERS; ++it) {
        halfstep(v01, v23, b01, b23, u01, u23, 0);
        halfstep(u01, u23, a01, a23, v01, v23, 1);
    }

    // ---- cost = u.(Mv); Mv = Hg(v) + W1*(T[r-1]+T[r+1]), T = v + 2*Hg(v) ----
    float vv[4][4], uu[4][4];
#pragma unroll
    for (int i = 0; i < 4; ++i) {
        UPK(vv[i][0], vv[i][1], v01[i]);
        UPK(vv[i][2], vv[i][3], v23[i]);
        UPK(uu[i][0], uu[i][1], u01[i]);
        UPK(uu[i][2], uu[i][3], u23[i]);
    }
    float HG[4][4], T[4][4];
#pragma unroll
    for (int i = 0; i < 4; ++i) {
        float lf = __shfl_up_sync(0xffffffffu, vv[i][3], 1, 16);
        float rt = __shfl_down_sync(0xffffffffu, vv[i][0], 1, 16);
        if (seg == 0)  lf = 0.f;
        if (seg == 15) rt = 0.f;
        HG[i][0] = W1 * (lf + vv[i][1]);
        HG[i][1] = W1 * (vv[i][0] + vv[i][2]);
        HG[i][2] = W1 * (vv[i][1] + vv[i][3]);
        HG[i][3] = W1 * (vv[i][2] + rt);
#pragma unroll
        for (int j = 0; j < 4; ++j) T[i][j] = fmaf(2.f, HG[i][j], vv[i][j]);
    }
    // slot 0 is safe to reuse: its last readers finished before halfstep-99's bar
    *(float4*)&HT[0][band + 1][c0] = make_float4(T[0][0], T[0][1], T[0][2], T[0][3]);
    *(float4*)&HB[0][band + 1][c0] = make_float4(T[3][0], T[3][1], T[3][2], T[3][3]);
    __syncthreads();
    const float4 u4 = *(const float4*)&HB[0][band][c0];
    const float4 d4 = *(const float4*)&HT[0][band + 2][c0];
    const float up[4] = {u4.x, u4.y, u4.z, u4.w};
    const float dn[4] = {d4.x, d4.y, d4.z, d4.w};

    float local = 0.f;
#pragma unroll
    for (int i = 0; i < 4; ++i) {
#pragma unroll
        for (int j = 0; j < 4; ++j) {
            const float tu = (i == 0) ? up[j] : T[i - 1][j];
            const float td = (i == 3) ? dn[j] : T[i + 1][j];
            const float mv = fmaf(W1, tu + td, HG[i][j]);
            local = fmaf(uu[i][j], mv, local);
        }
    }
    const float cost = blockReduceSum256(local, red);

    if (t == 0) {
        const bool valid = (asum > 0.5f) && (bsum > 0.5f);
        g_costs[bid] = valid ? cost : 0.f;
        __threadfence();
        const int prev = atomicAdd(&g_done, 1);
        if (prev == NBATCH - 1) {
            g_done = 0;
            __threadfence();
            float s = 0.f;
#pragma unroll
            for (int i = 0; i < NBATCH; ++i) s += g_costs[i];
            out[0] = s * (1.f / (float)NBATCH);
        }
    }
}

extern "C" void kernel_launch(void* const* d_in, const int* in_sizes, int n_in,
                              void* d_out, int out_size) {
    (void)in_sizes; (void)n_in; (void)out_size;
    const float* pred = (const float*)d_in[0];
    const float* gt   = (const float*)d_in[1];
    pool_kernel<<<512, 256>>>(pred, gt);
    sinkhorn_kernel<<<NBATCH, 256>>>((float*)d_out);
}

// round 9
// speedup vs baseline: 2.0482x; 1.1957x over previous
#include <cuda_runtime.h>

// Sinkhorn OT loss on 64x64 pooled grids. K = exp(-C/0.1) is exact (to fp32)
// as two 3-tap separable passes, W1 = exp(-10).
// R9: ZERO-COMMUNICATION domain overlap. Influence propagates 1 row/halfstep
// with weight W1, so a window edge treated as zero injects error
// <= C(100,h)*W1^h at depth h: for h=8 halo rows that is ~3e-24. Each batch is
// computed by 4 INDEPENDENT CTAs, each owning 16 rows and redundantly
// computing 8 halo rows on each side (32-row window). No cluster, no DSMEM,
// no cross-CTA sync in the loop; per-SM work halves vs the 1-CTA/batch design.
// Batch a/b sums come from pool-kernel partials, reduced in fixed order.

#define NBATCH 16
#define ITERS  50
#define EPS    1e-8f
#define W1     4.5399929762484854e-05f   // exp(-10)

__device__ float g_pooled[2][NBATCH][4096];
__device__ float g_psum[2][NBATCH][16];    // per pool-block partial sums
__device__ float g_costs[NBATCH * 4];
__device__ int   g_done;

// ---------------------------------------------------------------- reduce
__device__ __forceinline__ float blockReduceSum256(float val, float* red) {
#pragma unroll
    for (int o = 16; o; o >>= 1) val += __shfl_xor_sync(0xffffffffu, val, o);
    const int w = threadIdx.x >> 5, l = threadIdx.x & 31;
    __syncthreads();
    if (l == 0) red[w] = val;
    __syncthreads();
    float s = ((red[0] + red[1]) + (red[2] + red[3]))
            + ((red[4] + red[5]) + (red[6] + red[7]));
    __syncthreads();
    return s;
}

// ---------------------------------------------------------------- pooling
__global__ __launch_bounds__(256) void pool_kernel(const float* __restrict__ pred,
                                                   const float* __restrict__ gt) {
    __shared__ float red[8];
    const int bid    = blockIdx.x;          // 0..511
    const int tensor = bid >> 8;
    const int batch  = (bid >> 4) & 15;
    const int rb     = bid & 15;            // block of 4 pooled rows
    const float* src = (tensor ? gt : pred) + (size_t)batch * 262144;

    const int pr = rb * 4 + (threadIdx.x >> 6);
    const int pc = threadIdx.x & 63;
    const float4* p = (const float4*)(src + (size_t)pr * 4096 + pc * 8);

    float s = 0.f;
#pragma unroll
    for (int y = 0; y < 8; ++y) {
        float4 v0 = p[y * 128];
        float4 v1 = p[y * 128 + 1];
        s += (v0.x + v0.y) + (v0.z + v0.w) + (v1.x + v1.y) + (v1.z + v1.w);
    }
    g_pooled[tensor][batch][pr * 64 + pc] = s;

    const float tot = blockReduceSum256(s, red);
    if (threadIdx.x == 0) g_psum[tensor][batch][rb] = tot;
}

// ---------------------------------------------------------------- sinkhorn
__global__ __launch_bounds__(256, 1) void sinkhorn_kernel(float* __restrict__ out) {
    // seam rows, double-buffered by halfstep slot; index band+1; 0 & 17 = 0 pads
    __shared__ __align__(16) float HT[2][18][64];   // each band's H row 2b   (upper)
    __shared__ __align__(16) float HB[2][18][64];   // each band's H row 2b+1 (lower)
    __shared__ float red[8];

    const int t     = threadIdx.x;
    const int w     = t >> 5, l = t & 31;
    const int seg   = l & 15;
    const int band  = 2 * w + (l >> 4);    // 0..15, 2 window-rows each
    const int c0    = seg * 4;
    const int q     = blockIdx.x & 3;      // quarter index within batch
    const int batch = blockIdx.x >> 2;
    const int wstart = 16 * q - 8;         // window = rows wstart .. wstart+31
    const int r0    = wstart + 2 * band;   // this thread's first global row
    const bool own  = (band >= 4) && (band < 12);   // owned rows 16q..16q+15

    if (t < 64) {
        HT[0][17][t] = 0.f; HT[1][17][t] = 0.f;   // below window
        HB[0][0][t]  = 0.f; HB[1][0][t]  = 0.f;   // above window
    }

    // ---- batch-wide sums from pool partials (fixed linear order) ----
    float asum = 0.f, bsum = 0.f;
#pragma unroll
    for (int i = 0; i < 16; ++i) {
        asum += g_psum[0][batch][i];
        bsum += g_psum[1][batch][i];
    }
    const float ra  = 1.f / fmaxf(asum, 1e-8f);
    const float rbv = 1.f / fmaxf(bsum, 1e-8f);

    // ---- load window rows (zero outside the 64-row grid) ----
    float a[2][4], b[2][4], u[2][4], v[2][4];
#pragma unroll
    for (int i = 0; i < 2; ++i) {
        const int r = r0 + i;
        if ((unsigned)r < 64u) {
            const float4 x = *(const float4*)&g_pooled[0][batch][r * 64 + c0];
            const float4 y = *(const float4*)&g_pooled[1][batch][r * 64 + c0];
            a[i][0] = x.x * ra;  a[i][1] = x.y * ra;
            a[i][2] = x.z * ra;  a[i][3] = x.w * ra;
            b[i][0] = y.x * rbv; b[i][1] = y.y * rbv;
            b[i][2] = y.z * rbv; b[i][3] = y.w * rbv;
#pragma unroll
            for (int j = 0; j < 4; ++j) u[i][j] = 1.f;
        } else {
#pragma unroll
            for (int j = 0; j < 4; ++j) { a[i][j] = 0.f; b[i][j] = 0.f; u[i][j] = 0.f; }
        }
    }
    __syncthreads();   // pad init visible

    // out = tg / (Ve(He(in)) + eps); one __syncthreads per halfstep
    auto halfstep = [&](float (&o)[2][4], const float (&tg)[2][4],
                        const float (&in)[2][4], const int s) {
        float H0[4], H1[4];
        {
            float lf0 = __shfl_up_sync(0xffffffffu, in[0][3], 1, 16);
            float rt0 = __shfl_down_sync(0xffffffffu, in[0][0], 1, 16);
            float lf1 = __shfl_up_sync(0xffffffffu, in[1][3], 1, 16);
            float rt1 = __shfl_down_sync(0xffffffffu, in[1][0], 1, 16);
            if (seg == 0)  { lf0 = 0.f; lf1 = 0.f; }
            if (seg == 15) { rt0 = 0.f; rt1 = 0.f; }
            H0[0] = fmaf(W1, lf0 + in[0][1],      in[0][0]);
            H0[1] = fmaf(W1, in[0][0] + in[0][2], in[0][1]);
            H0[2] = fmaf(W1, in[0][1] + in[0][3], in[0][2]);
            H0[3] = fmaf(W1, in[0][2] + rt0,      in[0][3]);
            H1[0] = fmaf(W1, lf1 + in[1][1],      in[1][0]);
            H1[1] = fmaf(W1, in[1][0] + in[1][2], in[1][1]);
            H1[2] = fmaf(W1, in[1][1] + in[1][3], in[1][2]);
            H1[3] = fmaf(W1, in[1][2] + rt1,      in[1][3]);
        }
        *(float4*)&HT[s][band + 1][c0] = make_float4(H0[0], H0[1], H0[2], H0[3]);
        *(float4*)&HB[s][band + 1][c0] = make_float4(H1[0], H1[1], H1[2], H1[3]);
        __syncthreads();
        const float4 u4 = *(const float4*)&HB[s][band][c0];      // H row r0-1
        const float4 d4 = *(const float4*)&HT[s][band + 2][c0];  // H row r0+2
        const float up[4] = {u4.x, u4.y, u4.z, u4.w};
        const float dn[4] = {d4.x, d4.y, d4.z, d4.w};
#pragma unroll
        for (int j = 0; j < 4; ++j) {
            const float d0 = fmaf(W1, up[j] + H1[j], H0[j] + EPS);
            const float d1 = fmaf(W1, H0[j] + dn[j], H1[j] + EPS);
            o[0][j] = __fdividef(tg[0][j], d0);
            o[1][j] = __fdividef(tg[1][j], d1);
        }
    };

    for (int it = 0; it < ITERS; ++it) {
        halfstep(v, b, u, 0);
        halfstep(u, a, v, 1);
    }

    // ---- cost over OWNED rows: u.(Mv); Mv = Hg(v) + W1*(T[r-1]+T[r+1]),
    //      T = v + 2*Hg(v) ----
    float HG[2][4], T[2][4];
    {
        float lf0 = __shfl_up_sync(0xffffffffu, v[0][3], 1, 16);
        float rt0 = __shfl_down_sync(0xffffffffu, v[0][0], 1, 16);
        float lf1 = __shfl_up_sync(0xffffffffu, v[1][3], 1, 16);
        float rt1 = __shfl_down_sync(0xffffffffu, v[1][0], 1, 16);
        if (seg == 0)  { lf0 = 0.f; lf1 = 0.f; }
        if (seg == 15) { rt0 = 0.f; rt1 = 0.f; }
        HG[0][0] = W1 * (lf0 + v[0][1]);     HG[1][0] = W1 * (lf1 + v[1][1]);
        HG[0][1] = W1 * (v[0][0] + v[0][2]); HG[1][1] = W1 * (v[1][0] + v[1][2]);
        HG[0][2] = W1 * (v[0][1] + v[0][3]); HG[1][2] = W1 * (v[1][1] + v[1][3]);
        HG[0][3] = W1 * (v[0][2] + rt0);     HG[1][3] = W1 * (v[1][2] + rt1);
#pragma unroll
        for (int i = 0; i < 2; ++i)
#pragma unroll
            for (int j = 0; j < 4; ++j) T[i][j] = fmaf(2.f, HG[i][j], v[i][j]);
    }
    // slot 0 reuse is safe: its last readers synced inside the final s=1 halfstep
    *(float4*)&HT[0][band + 1][c0] = make_float4(T[0][0], T[0][1], T[0][2], T[0][3]);
    *(float4*)&HB[0][band + 1][c0] = make_float4(T[1][0], T[1][1], T[1][2], T[1][3]);
    __syncthreads();
    const float4 u4 = *(const float4*)&HB[0][band][c0];
    const float4 d4 = *(const float4*)&HT[0][band + 2][c0];
    const float up[4] = {u4.x, u4.y, u4.z, u4.w};
    const float dn[4] = {d4.x, d4.y, d4.z, d4.w};

    float local = 0.f;
#pragma unroll
    for (int j = 0; j < 4; ++j) {
        const float mv0 = fmaf(W1, up[j] + T[1][j], HG[0][j]);
        const float mv1 = fmaf(W1, T[0][j] + dn[j], HG[1][j]);
        local = fmaf(u[0][j], mv0, fmaf(u[1][j], mv1, local));
    }
    local = own ? local : 0.f;
    const float cost = blockReduceSum256(local, red);

    if (t == 0) {
        g_costs[blockIdx.x] = cost;
        __threadfence();
        const int prev = atomicAdd(&g_done, 1);
        if (prev == 4 * NBATCH - 1) {
            g_done = 0;
            __threadfence();
            float s = 0.f;
#pragma unroll
            for (int bb = 0; bb < NBATCH; ++bb) {
                float as = 0.f, bs = 0.f;
#pragma unroll
                for (int i = 0; i < 16; ++i) {
                    as += g_psum[0][bb][i];
                    bs += g_psum[1][bb][i];
                }
                const float c = (g_costs[4 * bb] + g_costs[4 * bb + 1])
                              + (g_costs[4 * bb + 2] + g_costs[4 * bb + 3]);
                s += ((as > 0.5f) && (bs > 0.5f)) ? c : 0.f;
            }
            out[0] = s * (1.f / (float)NBATCH);
        }
    }
}

extern "C" void kernel_launch(void* const* d_in, const int* in_sizes, int n_in,
                              void* d_out, int out_size) {
    (void)in_sizes; (void)n_in; (void)out_size;
    const float* pred = (const float*)d_in[0];
    const float* gt   = (const float*)d_in[1];
    pool_kernel<<<512, 256>>>(pred, gt);
    sinkhorn_kernel<<<NBATCH * 4, 256>>>((float*)d_out);
}

// round 10
// speedup vs baseline: 2.3629x; 1.1537x over previous
#include <cuda_runtime.h>

// Sinkhorn OT loss on 64x64 pooled grids. K = exp(-C/0.1) is exact (to fp32)
// as two 3-tap separable passes, W1 = exp(-10).
// R10: zero-communication domain overlap, finer split. 8 independent CTAs per
// batch; each owns 8 rows and redundantly computes a 16-row window (4+4 halo;
// edge error <= C(100,4)*W1^4 ~ 1.7e-11 -> invisible at fp32). CTA = 128
// threads / 4 warps: BAR spread covers 4 warps, each warp owns its SMSP's full
// issue bandwidth, per-SMSP instruction volume halves vs R9.

#define NBATCH 16
#define ITERS  50
#define EPS    1e-8f
#define W1     4.5399929762484854e-05f   // exp(-10)

__device__ float g_pooled[2][NBATCH][4096];
__device__ float g_psum[2][NBATCH][16];    // per pool-block partial sums
__device__ float g_costs[NBATCH * 8];
__device__ int   g_done;

// ---------------------------------------------------------------- pooling
__global__ __launch_bounds__(256) void pool_kernel(const float* __restrict__ pred,
                                                   const float* __restrict__ gt) {
    __shared__ float red[8];
    const int bid    = blockIdx.x;          // 0..511
    const int tensor = bid >> 8;
    const int batch  = (bid >> 4) & 15;
    const int rb     = bid & 15;            // block of 4 pooled rows
    const float* src = (tensor ? gt : pred) + (size_t)batch * 262144;

    const int pr = rb * 4 + (threadIdx.x >> 6);
    const int pc = threadIdx.x & 63;
    const float4* p = (const float4*)(src + (size_t)pr * 4096 + pc * 8);

    float s = 0.f;
#pragma unroll
    for (int y = 0; y < 8; ++y) {
        float4 v0 = p[y * 128];
        float4 v1 = p[y * 128 + 1];
        s += (v0.x + v0.y) + (v0.z + v0.w) + (v1.x + v1.y) + (v1.z + v1.w);
    }
    g_pooled[tensor][batch][pr * 64 + pc] = s;

    // block total (8 warps)
    float v = s;
#pragma unroll
    for (int o = 16; o; o >>= 1) v += __shfl_xor_sync(0xffffffffu, v, o);
    const int w = threadIdx.x >> 5, l = threadIdx.x & 31;
    if (l == 0) red[w] = v;
    __syncthreads();
    if (threadIdx.x == 0) {
        float tot = ((red[0] + red[1]) + (red[2] + red[3]))
                  + ((red[4] + red[5]) + (red[6] + red[7]));
        g_psum[tensor][batch][rb] = tot;
    }
}

// ---------------------------------------------------------------- sinkhorn
__device__ __forceinline__ float blockReduceSum128(float val, float* red) {
#pragma unroll
    for (int o = 16; o; o >>= 1) val += __shfl_xor_sync(0xffffffffu, val, o);
    const int w = threadIdx.x >> 5, l = threadIdx.x & 31;
    __syncthreads();
    if (l == 0) red[w] = val;
    __syncthreads();
    float s = (red[0] + red[1]) + (red[2] + red[3]);
    __syncthreads();
    return s;
}

__global__ __launch_bounds__(128, 1) void sinkhorn_kernel(float* __restrict__ out) {
    // seam rows, double-buffered by halfstep slot; index band+1; 0 & 9 = 0 pads
    __shared__ __align__(16) float HT[2][10][64];   // each band's H row 2b   (upper)
    __shared__ __align__(16) float HB[2][10][64];   // each band's H row 2b+1 (lower)
    __shared__ float red[4];

    const int t     = threadIdx.x;
    const int w     = t >> 5, l = t & 31;
    const int seg   = l & 15;
    const int band  = 2 * w + (l >> 4);    // 0..7, 2 window-rows each
    const int c0    = seg * 4;
    const int q     = blockIdx.x & 7;      // eighth index within batch
    const int batch = blockIdx.x >> 3;
    const int r0    = 8 * q - 4 + 2 * band;   // window = rows 8q-4 .. 8q+11
    const bool own  = (band >= 2) && (band < 6);   // owned rows 8q..8q+7

    if (t < 64) {
        HT[0][9][t] = 0.f; HT[1][9][t] = 0.f;   // below window
        HB[0][0][t] = 0.f; HB[1][0][t] = 0.f;   // above window
    }

    // ---- batch-wide sums from pool partials (fixed linear order) ----
    float asum = 0.f, bsum = 0.f;
#pragma unroll
    for (int i = 0; i < 16; ++i) {
        asum += g_psum[0][batch][i];
        bsum += g_psum[1][batch][i];
    }
    const float ra  = 1.f / fmaxf(asum, 1e-8f);
    const float rbv = 1.f / fmaxf(bsum, 1e-8f);

    // ---- load window rows (zero outside the 64-row grid) ----
    float a[2][4], b[2][4], u[2][4], v[2][4];
#pragma unroll
    for (int i = 0; i < 2; ++i) {
        const int r = r0 + i;
        if ((unsigned)r < 64u) {
            const float4 x = *(const float4*)&g_pooled[0][batch][r * 64 + c0];
            const float4 y = *(const float4*)&g_pooled[1][batch][r * 64 + c0];
            a[i][0] = x.x * ra;  a[i][1] = x.y * ra;
            a[i][2] = x.z * ra;  a[i][3] = x.w * ra;
            b[i][0] = y.x * rbv; b[i][1] = y.y * rbv;
            b[i][2] = y.z * rbv; b[i][3] = y.w * rbv;
#pragma unroll
            for (int j = 0; j < 4; ++j) u[i][j] = 1.f;
        } else {
#pragma unroll
            for (int j = 0; j < 4; ++j) { a[i][j] = 0.f; b[i][j] = 0.f; u[i][j] = 0.f; }
        }
    }
    __syncthreads();   // pad init visible

    // out = tg / (Ve(He(in)) + eps); one __syncthreads per halfstep
    auto halfstep = [&](float (&o)[2][4], const float (&tg)[2][4],
                        const float (&in)[2][4], const int s) {
        float H0[4], H1[4];
        {
            float lf0 = __shfl_up_sync(0xffffffffu, in[0][3], 1, 16);
            float rt0 = __shfl_down_sync(0xffffffffu, in[0][0], 1, 16);
            float lf1 = __shfl_up_sync(0xffffffffu, in[1][3], 1, 16);
            float rt1 = __shfl_down_sync(0xffffffffu, in[1][0], 1, 16);
            if (seg == 0)  { lf0 = 0.f; lf1 = 0.f; }
            if (seg == 15) { rt0 = 0.f; rt1 = 0.f; }
            H0[0] = fmaf(W1, lf0 + in[0][1],      in[0][0]);
            H0[1] = fmaf(W1, in[0][0] + in[0][2], in[0][1]);
            H0[2] = fmaf(W1, in[0][1] + in[0][3], in[0][2]);
            H0[3] = fmaf(W1, in[0][2] + rt0,      in[0][3]);
            H1[0] = fmaf(W1, lf1 + in[1][1],      in[1][0]);
            H1[1] = fmaf(W1, in[1][0] + in[1][2], in[1][1]);
            H1[2] = fmaf(W1, in[1][1] + in[1][3], in[1][2]);
            H1[3] = fmaf(W1, in[1][2] + rt1,      in[1][3]);
        }
        *(float4*)&HT[s][band + 1][c0] = make_float4(H0[0], H0[1], H0[2], H0[3]);
        *(float4*)&HB[s][band + 1][c0] = make_float4(H1[0], H1[1], H1[2], H1[3]);
        __syncthreads();
        const float4 u4 = *(const float4*)&HB[s][band][c0];      // H row r0-1
        const float4 d4 = *(const float4*)&HT[s][band + 2][c0];  // H row r0+2
        const float up[4] = {u4.x, u4.y, u4.z, u4.w};
        const float dn[4] = {d4.x, d4.y, d4.z, d4.w};
#pragma unroll
        for (int j = 0; j < 4; ++j) {
            const float d0 = fmaf(W1, up[j] + H1[j], H0[j] + EPS);
            const float d1 = fmaf(W1, H0[j] + dn[j], H1[j] + EPS);
            o[0][j] = __fdividef(tg[0][j], d0);
            o[1][j] = __fdividef(tg[1][j], d1);
        }
    };

    for (int it = 0; it < ITERS; ++it) {
        halfstep(v, b, u, 0);
        halfstep(u, a, v, 1);
    }

    // ---- cost over OWNED rows: u.(Mv); Mv = Hg(v) + W1*(T[r-1]+T[r+1]),
    //      T = v + 2*Hg(v) ----
    float HG[2][4], T[2][4];
    {
        float lf0 = __shfl_up_sync(0xffffffffu, v[0][3], 1, 16);
        float rt0 = __shfl_down_sync(0xffffffffu, v[0][0], 1, 16);
        float lf1 = __shfl_up_sync(0xffffffffu, v[1][3], 1, 16);
        float rt1 = __shfl_down_sync(0xffffffffu, v[1][0], 1, 16);
        if (seg == 0)  { lf0 = 0.f; lf1 = 0.f; }
        if (seg == 15) { rt0 = 0.f; rt1 = 0.f; }
        HG[0][0] = W1 * (lf0 + v[0][1]);     HG[1][0] = W1 * (lf1 + v[1][1]);
        HG[0][1] = W1 * (v[0][0] + v[0][2]); HG[1][1] = W1 * (v[1][0] + v[1][2]);
        HG[0][2] = W1 * (v[0][1] + v[0][3]); HG[1][2] = W1 * (v[1][1] + v[1][3]);
        HG[0][3] = W1 * (v[0][2] + rt0);     HG[1][3] = W1 * (v[1][2] + rt1);
#pragma unroll
        for (int i = 0; i < 2; ++i)
#pragma unroll
            for (int j = 0; j < 4; ++j) T[i][j] = fmaf(2.f, HG[i][j], v[i][j]);
    }
    // slot 0 reuse is safe: its last readers synced inside the final s=1 halfstep
    *(float4*)&HT[0][band + 1][c0] = make_float4(T[0][0], T[0][1], T[0][2], T[0][3]);
    *(float4*)&HB[0][band + 1][c0] = make_float4(T[1][0], T[1][1], T[1][2], T[1][3]);
    __syncthreads();
    const float4 u4 = *(const float4*)&HB[0][band][c0];
    const float4 d4 = *(const float4*)&HT[0][band + 2][c0];
    const float up[4] = {u4.x, u4.y, u4.z, u4.w};
    const float dn[4] = {d4.x, d4.y, d4.z, d4.w};

    float local = 0.f;
#pragma unroll
    for (int j = 0; j < 4; ++j) {
        const float mv0 = fmaf(W1, up[j] + T[1][j], HG[0][j]);
        const float mv1 = fmaf(W1, T[0][j] + dn[j], HG[1][j]);
        local = fmaf(u[0][j], mv0, fmaf(u[1][j], mv1, local));
    }
    local = own ? local : 0.f;
    const float cost = blockReduceSum128(local, red);

    if (t == 0) {
        g_costs[blockIdx.x] = cost;
        __threadfence();
        const int prev = atomicAdd(&g_done, 1);
        if (prev == 8 * NBATCH - 1) {
            g_done = 0;
            __threadfence();
            float s = 0.f;
#pragma unroll
            for (int bb = 0; bb < NBATCH; ++bb) {
                float as = 0.f, bs = 0.f;
#pragma unroll
                for (int i = 0; i < 16; ++i) {
                    as += g_psum[0][bb][i];
                    bs += g_psum[1][bb][i];
                }
                float c = 0.f;
#pragma unroll
                for (int k = 0; k < 8; ++k) c += g_costs[8 * bb + k];
                s += ((as > 0.5f) && (bs > 0.5f)) ? c : 0.f;
            }
            out[0] = s * (1.f / (float)NBATCH);
        }
    }
}

extern "C" void kernel_launch(void* const* d_in, const int* in_sizes, int n_in,
                              void* d_out, int out_size) {
    (void)in_sizes; (void)n_in; (void)out_size;
    const float* pred = (const float*)d_in[0];
    const float* gt   = (const float*)d_in[1];
    pool_kernel<<<512, 256>>>(pred, gt);
    sinkhorn_kernel<<<NBATCH * 8, 128>>>((float*)d_out);
}